// round 1
// baseline (speedup 1.0000x reference)
#include <cuda_runtime.h>
#include <math.h>
#include <stdint.h>

#define Bv 4
#define Lv 4096
#define Dv 512
#define Pv 128
#define Vv 8
#define Mv (Bv*Lv)          // 16384
#define NCv 32
#define LCv (Lv/NCv)        // 128
#define PI_F 3.14159265358979323846f
#define INV_SQRT_D 0.044194173824159216f   // 1/sqrt(512)
#define INV_SQRT_P 0.08838834764831845f    // 1/sqrt(128)

// ---------------- scratch (static device globals; no runtime alloc) ----------------
__device__ float g_xcat[(size_t)Mv*1024];     // [x | context_avg]
__device__ float g_v1[(size_t)Mv*512];
__device__ float g_mag[(size_t)Mv*512];       // sigmoid(x@w_m+b)*|ms|
__device__ float g_qd[(size_t)Mv*512];        // x@w_q+b_q
__device__ float g_qp[(size_t)Mv*128];        // query_phase
__device__ float g_sp[(size_t)Mv*128];        // storage_phase
__device__ float g_cqp[(size_t)Mv*128], g_sqp[(size_t)Mv*128];
__device__ float g_csp[(size_t)Mv*128], g_ssp[(size_t)Mv*128];
__device__ float g_gv[(size_t)Mv*8], g_gate[Mv];
__device__ float g_s1g[(size_t)Mv*512];
__device__ float g_cphi[(size_t)Lv*Dv], g_sphi[(size_t)Lv*Dv];
__device__ float g_posret[(size_t)Mv*512];
__device__ float g_ccat[(size_t)Mv*1024];     // [pos_out | kv_out]
__device__ float g_ln[(size_t)Mv*1024];
__device__ float g_h1[(size_t)Mv*1024];
__device__ float g_kvr[(size_t)Mv*8];
// scan partials
__device__ float g_pctx[Bv*NCv*Dv];
__device__ float g_pmc[Bv*NCv*Dv], g_pms[Bv*NCv*Dv], g_pmm[Bv*NCv*Dv];
__device__ float g_pkc[Bv*NCv*Pv*Vv], g_pks[Bv*NCv*Pv*Vv], g_pg[Bv*NCv];

// ---------------- generic fp32 GEMM: C = epi(A@W + bias) ----------------
// A: MxK row-major (lda=K), W: KxN row-major, grid=(N/128, M/128), 256 thr
// epi: 0 none, 1 sigmoid*|*eptr|, 2 exact gelu, 3 tanh*PI, 4 +eptr[gm*ldc+gn]
__global__ void __launch_bounds__(256) sgemm_kernel(
    const float* __restrict__ A, const float* __restrict__ W,
    const float* __restrict__ bias, float* __restrict__ C,
    int N, int K, int ldc, int epi, const float* __restrict__ eptr)
{
    __shared__ float As[8][128];
    __shared__ float Bs[8][128];
    const int tid = threadIdx.x;
    const int m0 = blockIdx.y * 128;
    const int n0 = blockIdx.x * 128;
    const int arow = tid >> 1;
    const int acol = (tid & 1) * 4;
    const int brow = tid >> 5;
    const int bcol = (tid & 31) * 4;
    const int tm = (tid >> 4) * 8;
    const int tn = (tid & 15) * 8;

    float acc[8][8];
#pragma unroll
    for (int i = 0; i < 8; i++)
#pragma unroll
        for (int j = 0; j < 8; j++) acc[i][j] = 0.f;

    const float* Ab = A + (size_t)(m0 + arow) * K + acol;
    const float* Wb = W + (size_t)brow * N + n0 + bcol;

    for (int k0 = 0; k0 < K; k0 += 8) {
        float4 av = *(const float4*)(Ab + k0);
        float4 bv = *(const float4*)(Wb + (size_t)k0 * N);
        As[acol + 0][arow] = av.x;
        As[acol + 1][arow] = av.y;
        As[acol + 2][arow] = av.z;
        As[acol + 3][arow] = av.w;
        *(float4*)&Bs[brow][bcol] = bv;
        __syncthreads();
#pragma unroll
        for (int kk = 0; kk < 8; kk++) {
            float4 a0 = *(const float4*)&As[kk][tm];
            float4 a1 = *(const float4*)&As[kk][tm + 4];
            float4 b0 = *(const float4*)&Bs[kk][tn];
            float4 b1 = *(const float4*)&Bs[kk][tn + 4];
            float aa[8] = {a0.x, a0.y, a0.z, a0.w, a1.x, a1.y, a1.z, a1.w};
            float bb[8] = {b0.x, b0.y, b0.z, b0.w, b1.x, b1.y, b1.z, b1.w};
#pragma unroll
            for (int i = 0; i < 8; i++)
#pragma unroll
                for (int j = 0; j < 8; j++) acc[i][j] += aa[i] * bb[j];
        }
        __syncthreads();
    }

    float bb[8];
#pragma unroll
    for (int j = 0; j < 8; j++) bb[j] = bias[n0 + tn + j];
    float scale = (epi == 1) ? fabsf(*eptr) : 0.f;

#pragma unroll
    for (int i = 0; i < 8; i++) {
        int gm = m0 + tm + i;
#pragma unroll
        for (int j = 0; j < 8; j++) {
            int gn = n0 + tn + j;
            float v = acc[i][j] + bb[j];
            if (epi == 1)      v = scale / (1.f + expf(-v));
            else if (epi == 2) v = 0.5f * v * (1.f + erff(v * 0.70710678118654752f));
            else if (epi == 3) v = tanhf(v) * PI_F;
            else if (epi == 4) v += eptr[(size_t)gm * ldc + gn];
            C[(size_t)gm * ldc + gn] = v;
        }
    }
}

// ---------------- phi sincos precompute ----------------
__global__ void phi_kernel(const float* __restrict__ pos) {
    int idx = blockIdx.x * blockDim.x + threadIdx.x;
    if (idx < Lv * Dv) {
        float s, c;
        sincosf(pos[idx], &s, &c);
        g_cphi[idx] = c; g_sphi[idx] = s;
    }
}

// ---------------- context_avg chunked scan + xcat build ----------------
__global__ void ctx_p1(const float* __restrict__ x) {
    int bc = blockIdx.x; int b = bc >> 5, c = bc & 31;
    int d = blockIdx.y * 128 + threadIdx.x;
    const float* xp = x + ((size_t)(b * Lv + c * LCv)) * Dv + d;
    float s = 0.f;
    for (int i = 0; i < LCv; i++) s += xp[(size_t)i * Dv];
    g_pctx[(size_t)bc * Dv + d] = s;
}
__global__ void ctx_p2() {
    int idx = blockIdx.x * blockDim.x + threadIdx.x;
    if (idx >= Bv * Dv) return;
    int b = idx / Dv, d = idx % Dv;
    float run = 0.f;
    for (int c = 0; c < NCv; c++) {
        size_t o = ((size_t)(b * NCv + c)) * Dv + d;
        float t = g_pctx[o]; g_pctx[o] = run; run += t;
    }
}
__global__ void ctx_p3(const float* __restrict__ x) {
    int bc = blockIdx.x; int b = bc >> 5, c = bc & 31;
    int d = blockIdx.y * 128 + threadIdx.x;
    const float* xp = x + ((size_t)(b * Lv + c * LCv)) * Dv + d;
    float s = g_pctx[(size_t)bc * Dv + d];
    for (int i = 0; i < LCv; i++) {
        int l = c * LCv + i;
        float xv = xp[(size_t)i * Dv];
        s += xv;
        size_t row = (size_t)(b * Lv + l);
        g_xcat[row * 1024 + d] = xv;
        g_xcat[row * 1024 + 512 + d] = s / (float)(l + 1);
    }
}

// ---------------- values*gate fused small-N GEMM (N=8 + N=1) ----------------
__global__ void __launch_bounds__(256) vg_kernel(
    const float* __restrict__ x, const float* __restrict__ w_ve,
    const float* __restrict__ b_ve, const float* __restrict__ w_g,
    const float* __restrict__ b_g)
{
    __shared__ float sw[8 * 512];
    __shared__ float sg[512];
    int tid = threadIdx.x;
    for (int idx = tid; idx < 512 * 8; idx += 256) {
        int k = idx >> 3, v = idx & 7;
        sw[v * 512 + k] = w_ve[idx];
    }
    for (int idx = tid; idx < 512; idx += 256) sg[idx] = w_g[idx];
    __syncthreads();
    int lane = tid & 31, w = tid >> 5;
    int m = blockIdx.x * 8 + w;
    const float* xr = x + (size_t)m * 512;
    float acc[8] = {0, 0, 0, 0, 0, 0, 0, 0}, ag = 0.f;
    for (int j = 0; j < 16; j++) {
        int k = lane + 32 * j;
        float xk = xr[k];
#pragma unroll
        for (int v = 0; v < 8; v++) acc[v] += xk * sw[v * 512 + k];
        ag += xk * sg[k];
    }
#pragma unroll
    for (int o = 16; o; o >>= 1) {
#pragma unroll
        for (int v = 0; v < 8; v++) acc[v] += __shfl_xor_sync(0xffffffffu, acc[v], o);
        ag += __shfl_xor_sync(0xffffffffu, ag, o);
    }
    if (lane == 0) {
        float gate = 1.f / (1.f + expf(-(ag + b_g[0])));
        g_gate[m] = gate;
#pragma unroll
        for (int v = 0; v < 8; v++) g_gv[(size_t)m * 8 + v] = (acc[v] + b_ve[v]) * gate;
    }
}

// ---------------- sincos for query/storage phases ----------------
__global__ void ew_sincos() {
    int idx = blockIdx.x * blockDim.x + threadIdx.x;
    if (idx < Mv * 128) {
        float s, c;
        sincosf(g_qp[idx], &s, &c);
        g_cqp[idx] = c; g_sqp[idx] = s;
        sincosf(g_sp[idx], &s, &c);
        g_csp[idx] = c; g_ssp[idx] = s;
    }
}

// ---------------- mem1 chunked scan + fused pos_ret ----------------
__global__ void mem1_p1() {
    int bc = blockIdx.x; int b = bc >> 5, c = bc & 31;
    int d = blockIdx.y * 128 + threadIdx.x;
    size_t base = ((size_t)(b * Lv + c * LCv)) * Dv + d;
    float sc = 0.f, ss = 0.f, sm = 0.f;
    for (int i = 0; i < LCv; i++) {
        int lg = c * LCv + i;
        float mag = g_mag[base + (size_t)i * Dv];
        float v1  = g_v1[base + (size_t)i * Dv];
        float w = mag * v1;
        size_t pidx = (size_t)lg * Dv + d;
        sc += w * g_cphi[pidx];
        ss += w * g_sphi[pidx];
        sm += mag;
    }
    size_t o = (size_t)bc * Dv + d;
    g_pmc[o] = sc; g_pms[o] = ss; g_pmm[o] = sm;
}
__global__ void mem1_p2() {
    int idx = blockIdx.x * blockDim.x + threadIdx.x;
    if (idx >= Bv * Dv) return;
    int b = idx / Dv, d = idx % Dv;
    float r1 = 0.f, r2 = 0.f, r3 = 0.f;
    for (int c = 0; c < NCv; c++) {
        size_t o = ((size_t)(b * NCv + c)) * Dv + d;
        float t1 = g_pmc[o]; g_pmc[o] = r1; r1 += t1;
        float t2 = g_pms[o]; g_pms[o] = r2; r2 += t2;
        float t3 = g_pmm[o]; g_pmm[o] = r3; r3 += t3;
    }
}
__global__ void mem1_p3(const float* __restrict__ pos) {
    int bc = blockIdx.x; int b = bc >> 5, c = bc & 31;
    int d = blockIdx.y * 128 + threadIdx.x;
    size_t base = ((size_t)(b * Lv + c * LCv)) * Dv + d;
    size_t po = (size_t)bc * Dv + d;
    float sc = g_pmc[po], ss = g_pms[po], sm = g_pmm[po];
    for (int i = 0; i < LCv; i++) {
        int lg = c * LCv + i;
        float mag = g_mag[base + (size_t)i * Dv];
        float v1  = g_v1[base + (size_t)i * Dv];
        float w = mag * v1;
        size_t pidx = (size_t)lg * Dv + d;
        sc += w * g_cphi[pidx];
        ss += w * g_sphi[pidx];
        sm += mag;
        float ph = pos[pidx] + g_qd[base + (size_t)i * Dv];
        float sq, cq;
        sincosf(ph, &sq, &cq);
        g_posret[base + (size_t)i * Dv] =
            (sc * cq + ss * sq) * rsqrtf(sm + 1e-8f) * INV_SQRT_D;
    }
}

// ---------------- kv phasor scan (state PxVx2) + fused retrieval ----------------
__global__ void __launch_bounds__(256) kv_p1() {
    __shared__ float s_csp[128], s_ssp[128], s_gv[8];
    int bc = blockIdx.x; int b = bc >> 5, c = bc & 31;
    int tid = threadIdx.x;
    int v = tid & 7, p_base = (tid >> 3) * 4;
    float aC[4] = {0, 0, 0, 0}, aS[4] = {0, 0, 0, 0};
    float gs = 0.f;
    for (int i = 0; i < LCv; i++) {
        int m = b * Lv + c * LCv + i;
        if (tid < 128) s_csp[tid] = g_csp[(size_t)m * 128 + tid];
        else           s_ssp[tid - 128] = g_ssp[(size_t)m * 128 + (tid - 128)];
        if (tid < 8) s_gv[tid] = g_gv[(size_t)m * 8 + tid];
        if (tid == 0) gs += g_gate[m];
        __syncthreads();
        float gvv = s_gv[v];
#pragma unroll
        for (int j = 0; j < 4; j++) {
            aC[j] += s_csp[p_base + j] * gvv;
            aS[j] += s_ssp[p_base + j] * gvv;
        }
        __syncthreads();
    }
#pragma unroll
    for (int j = 0; j < 4; j++) {
        size_t o = (size_t)bc * 1024 + (size_t)(p_base + j) * 8 + v;
        g_pkc[o] = aC[j]; g_pks[o] = aS[j];
    }
    if (tid == 0) g_pg[bc] = gs;
}
__global__ void kv_p2() {
    int idx = blockIdx.x * blockDim.x + threadIdx.x;
    if (idx < Bv * Pv * Vv) {
        int b = idx >> 10, pv = idx & 1023;
        float rc = 0.f, rs = 0.f;
        for (int c = 0; c < NCv; c++) {
            size_t o = ((size_t)(b * NCv + c)) * 1024 + pv;
            float tc = g_pkc[o]; g_pkc[o] = rc; rc += tc;
            float ts = g_pks[o]; g_pks[o] = rs; rs += ts;
        }
    }
    if (idx < Bv) {
        float rg = 0.f;
        for (int c = 0; c < NCv; c++) {
            size_t o = (size_t)idx * NCv + c;
            float t = g_pg[o]; g_pg[o] = rg; rg += t;
        }
    }
}
__global__ void __launch_bounds__(256) kv_p3() {
    __shared__ float s_csp[128], s_ssp[128], s_cqp[128], s_sqp[128], s_gv[8];
    __shared__ float s_r[64];
    __shared__ float s_inv;
    int bc = blockIdx.x; int b = bc >> 5, c = bc & 31;
    int tid = threadIdx.x;
    int v = tid & 7, p_base = (tid >> 3) * 4;
    float aC[4], aS[4];
#pragma unroll
    for (int j = 0; j < 4; j++) {
        size_t o = (size_t)bc * 1024 + (size_t)(p_base + j) * 8 + v;
        aC[j] = g_pkc[o]; aS[j] = g_pks[o];
    }
    float gsum = (tid == 0) ? g_pg[bc] : 0.f;
    for (int i = 0; i < LCv; i++) {
        int m = b * Lv + c * LCv + i;
        if (tid < 128) {
            s_csp[tid] = g_csp[(size_t)m * 128 + tid];
            s_cqp[tid] = g_cqp[(size_t)m * 128 + tid];
        } else {
            int t = tid - 128;
            s_ssp[t] = g_ssp[(size_t)m * 128 + t];
            s_sqp[t] = g_sqp[(size_t)m * 128 + t];
        }
        if (tid < 8) s_gv[tid] = g_gv[(size_t)m * 8 + tid];
        if (tid == 0) {
            gsum += g_gate[m];
            s_inv = rsqrtf(fmaxf(gsum, 1.0f));
        }
        __syncthreads();
        float gvv = s_gv[v];
        float pr = 0.f;
#pragma unroll
        for (int j = 0; j < 4; j++) {
            int p = p_base + j;
            aC[j] += s_csp[p] * gvv;
            aS[j] += s_ssp[p] * gvv;
            pr += s_cqp[p] * aC[j] + s_sqp[p] * aS[j];
        }
        pr += __shfl_xor_sync(0xffffffffu, pr, 8);
        pr += __shfl_xor_sync(0xffffffffu, pr, 16);
        if ((tid & 31) < 8) s_r[(tid >> 5) * 8 + (tid & 7)] = pr;
        __syncthreads();
        if (tid < 8) {
            float accv = 0.f;
#pragma unroll
            for (int w = 0; w < 8; w++) accv += s_r[w * 8 + tid];
            g_kvr[(size_t)m * 8 + tid] = accv * s_inv * INV_SQRT_P;
        }
        __syncthreads();
    }
}

// ---------------- kv_out = kvr @ w_kv + b_kv (K=8) ----------------
__global__ void __launch_bounds__(256) kvout_kernel(
    const float* __restrict__ w_kv, const float* __restrict__ b_kv)
{
    int tid = threadIdx.x;
    float wk0[8], wk1[8];
#pragma unroll
    for (int k = 0; k < 8; k++) {
        wk0[k] = w_kv[k * 512 + tid];
        wk1[k] = w_kv[k * 512 + tid + 256];
    }
    float bb0 = b_kv[tid], bb1 = b_kv[tid + 256];
    int m0 = blockIdx.x * 32;
    for (int r = 0; r < 32; r++) {
        int m = m0 + r;
        const float* kv = g_kvr + (size_t)m * 8;
        float o0 = bb0, o1 = bb1;
#pragma unroll
        for (int k = 0; k < 8; k++) {
            float kvk = __ldg(&kv[k]);
            o0 += kvk * wk0[k];
            o1 += kvk * wk1[k];
        }
        g_ccat[(size_t)m * 1024 + 512 + tid] = o0;
        g_ccat[(size_t)m * 1024 + 768 + tid] = o1;
    }
}

// ---------------- LayerNorm over combined (1024) ----------------
__global__ void __launch_bounds__(256) ln_kernel(
    const float* __restrict__ lng, const float* __restrict__ lnb)
{
    int m = blockIdx.x, tid = threadIdx.x;
    const float4* row = (const float4*)(g_ccat + (size_t)m * 1024);
    float4 val = row[tid];
    float s = val.x + val.y + val.z + val.w;
    float q = val.x * val.x + val.y * val.y + val.z * val.z + val.w * val.w;
#pragma unroll
    for (int o = 16; o; o >>= 1) {
        s += __shfl_xor_sync(0xffffffffu, s, o);
        q += __shfl_xor_sync(0xffffffffu, q, o);
    }
    __shared__ float ss[8], sq[8];
    __shared__ float smu, srs;
    if ((tid & 31) == 0) { ss[tid >> 5] = s; sq[tid >> 5] = q; }
    __syncthreads();
    if (tid == 0) {
        float S = 0.f, Q = 0.f;
#pragma unroll
        for (int w = 0; w < 8; w++) { S += ss[w]; Q += sq[w]; }
        float mu = S * (1.f / 1024.f);
        float var = Q * (1.f / 1024.f) - mu * mu;
        smu = mu; srs = rsqrtf(var + 1e-5f);
    }
    __syncthreads();
    float mu = smu, rs = srs;
    float4 g4 = ((const float4*)lng)[tid];
    float4 b4 = ((const float4*)lnb)[tid];
    float4 o;
    o.x = (val.x - mu) * rs * g4.x + b4.x;
    o.y = (val.y - mu) * rs * g4.y + b4.y;
    o.z = (val.z - mu) * rs * g4.z + b4.z;
    o.w = (val.w - mu) * rs * g4.w + b4.w;
    ((float4*)(g_ln + (size_t)m * 1024))[tid] = o;
}

// ---------------- launch ----------------
extern "C" void kernel_launch(void* const* d_in, const int* in_sizes, int n_in,
                              void* d_out, int out_size)
{
    const float* x    = (const float*)d_in[0];
    const float* pos  = (const float*)d_in[1];
    const float* ms   = (const float*)d_in[2];
    const float* w_v  = (const float*)d_in[3];
    const float* b_v  = (const float*)d_in[4];
    const float* w_o  = (const float*)d_in[5];
    const float* b_o  = (const float*)d_in[6];
    const float* w_m  = (const float*)d_in[7];
    const float* b_m  = (const float*)d_in[8];
    const float* w_q  = (const float*)d_in[9];
    const float* b_q  = (const float*)d_in[10];
    const float* w_ke = (const float*)d_in[11];
    const float* b_ke = (const float*)d_in[12];
    const float* w_ve = (const float*)d_in[13];
    const float* b_ve = (const float*)d_in[14];
    const float* w_s1 = (const float*)d_in[15];
    const float* b_s1 = (const float*)d_in[16];
    const float* w_s2 = (const float*)d_in[17];
    const float* b_s2 = (const float*)d_in[18];
    const float* w_g  = (const float*)d_in[19];
    const float* b_g  = (const float*)d_in[20];
    const float* w_kv = (const float*)d_in[21];
    const float* b_kv = (const float*)d_in[22];
    const float* lng  = (const float*)d_in[23];
    const float* lnb  = (const float*)d_in[24];
    const float* w_t1 = (const float*)d_in[25];
    const float* b_t1 = (const float*)d_in[26];
    const float* w_t2 = (const float*)d_in[27];
    const float* b_t2 = (const float*)d_in[28];
    float* out = (float*)d_out;

    float *p_xcat, *p_v1, *p_mag, *p_qd, *p_qp, *p_sp, *p_s1g, *p_posret,
          *p_ccat, *p_ln, *p_h1;
    cudaGetSymbolAddress((void**)&p_xcat, g_xcat);
    cudaGetSymbolAddress((void**)&p_v1, g_v1);
    cudaGetSymbolAddress((void**)&p_mag, g_mag);
    cudaGetSymbolAddress((void**)&p_qd, g_qd);
    cudaGetSymbolAddress((void**)&p_qp, g_qp);
    cudaGetSymbolAddress((void**)&p_sp, g_sp);
    cudaGetSymbolAddress((void**)&p_s1g, g_s1g);
    cudaGetSymbolAddress((void**)&p_posret, g_posret);
    cudaGetSymbolAddress((void**)&p_ccat, g_ccat);
    cudaGetSymbolAddress((void**)&p_ln, g_ln);
    cudaGetSymbolAddress((void**)&p_h1, g_h1);

    dim3 gScan(Bv * NCv, Dv / 128);
    dim3 g512(512 / 128, Mv / 128);
    dim3 g128(1, Mv / 128);
    dim3 g1024(1024 / 128, Mv / 128);

    // phi sincos + context scan
    phi_kernel<<<(Lv * Dv + 255) / 256, 256>>>(pos);
    ctx_p1<<<gScan, 128>>>(x);
    ctx_p2<<<(Bv * Dv + 255) / 256, 256>>>();
    ctx_p3<<<gScan, 128>>>(x);

    // projections
    sgemm_kernel<<<g512, 256>>>(x, w_v, b_v, p_v1, 512, 512, 512, 0, nullptr);
    sgemm_kernel<<<g512, 256>>>(x, w_m, b_m, p_mag, 512, 512, 512, 1, ms);
    sgemm_kernel<<<g512, 256>>>(x, w_q, b_q, p_qd, 512, 512, 512, 0, nullptr);
    sgemm_kernel<<<g128, 256>>>(x, w_ke, b_ke, p_qp, 128, 512, 128, 3, nullptr);
    vg_kernel<<<Mv / 8, 256>>>(x, w_ve, b_ve, w_g, b_g);
    sgemm_kernel<<<g512, 256>>>(p_xcat, w_s1, b_s1, p_s1g, 512, 1024, 512, 2, nullptr);
    sgemm_kernel<<<g128, 256>>>(p_s1g, w_s2, b_s2, p_sp, 128, 512, 128, 3, nullptr);
    ew_sincos<<<(Mv * 128 + 255) / 256, 256>>>();

    // mem1 scan + pos_ret + pos_out
    mem1_p1<<<gScan, 128>>>();
    mem1_p2<<<(Bv * Dv + 255) / 256, 256>>>();
    mem1_p3<<<gScan, 128>>>(pos);
    sgemm_kernel<<<g512, 256>>>(p_posret, w_o, b_o, p_ccat, 512, 512, 1024, 0, nullptr);

    // kv scan + retrieval + kv_out
    kv_p1<<<Bv * NCv, 256>>>();
    kv_p2<<<(Bv * Pv * Vv + 255) / 256, 256>>>();
    kv_p3<<<Bv * NCv, 256>>>();
    kvout_kernel<<<Mv / 32, 256>>>(w_kv, b_kv);

    // LN + output MLP + residual
    ln_kernel<<<Mv, 256>>>(lng, lnb);
    sgemm_kernel<<<g1024, 256>>>(p_ln, w_t1, b_t1, p_h1, 1024, 1024, 1024, 2, nullptr);
    sgemm_kernel<<<g512, 256>>>(p_h1, w_t2, b_t2, out, 512, 1024, 512, 4, x);
}

// round 4
// speedup vs baseline: 2.4845x; 2.4845x over previous
#include <cuda_runtime.h>
#include <math.h>
#include <stdint.h>

#define Bv 4
#define Lv 4096
#define Dv 512
#define Pv 128
#define Vv 8
#define Mv (Bv*Lv)          // 16384
#define NCv 32
#define LCv (Lv/NCv)        // 128
#define PI_F 3.14159265358979323846f
#define INV_SQRT_D 0.044194173824159216f   // 1/sqrt(512)
#define INV_SQRT_P 0.08838834764831845f    // 1/sqrt(128)

// ================= helpers =================
__device__ __forceinline__ uint32_t smem_u32(const void* p) {
    uint32_t a;
    asm("{ .reg .u64 t; cvta.to.shared.u64 t, %1; cvt.u32.u64 %0, t; }" : "=r"(a) : "l"(p));
    return a;
}
__device__ __forceinline__ void cp16(uint32_t s, const void* g) {
    asm volatile("cp.async.cg.shared.global [%0], [%1], 16;" :: "r"(s), "l"(g) : "memory");
}
#define CP_COMMIT() asm volatile("cp.async.commit_group;" ::: "memory")
#define CP_WAIT1()  asm volatile("cp.async.wait_group 1;" ::: "memory")
#define CP_WAIT0()  asm volatile("cp.async.wait_group 0;" ::: "memory")

__device__ __forceinline__ uint32_t f2tf32(float v) {
    uint32_t u;
    asm("cvt.rna.tf32.f32 %0, %1;" : "=r"(u) : "f"(v));
    return u;
}
__device__ __forceinline__ void mma_tf32(float* c,
    uint32_t a0, uint32_t a1, uint32_t a2, uint32_t a3,
    uint32_t b0, uint32_t b1)
{
    asm volatile(
        "mma.sync.aligned.m16n8k8.row.col.f32.tf32.tf32.f32 "
        "{%0,%1,%2,%3}, {%4,%5,%6,%7}, {%8,%9}, {%0,%1,%2,%3};"
        : "+f"(c[0]), "+f"(c[1]), "+f"(c[2]), "+f"(c[3])
        : "r"(a0), "r"(a1), "r"(a2), "r"(a3), "r"(b0), "r"(b1));
}

// ================= scratch =================
__device__ float g_xcat[(size_t)Mv*1024];
__device__ float g_v1[(size_t)Mv*512];
__device__ float g_mag[(size_t)Mv*512];
__device__ float g_qd[(size_t)Mv*512];
__device__ float g_cqp[(size_t)Mv*128], g_sqp[(size_t)Mv*128];
__device__ float g_csp[(size_t)Mv*128], g_ssp[(size_t)Mv*128];
__device__ float g_gv[(size_t)Mv*8], g_gate[Mv];
__device__ float g_s1g[(size_t)Mv*512];
__device__ float g_cphi[(size_t)Lv*Dv], g_sphi[(size_t)Lv*Dv];
__device__ float g_posret[(size_t)Mv*512];
__device__ float g_ccat[(size_t)Mv*1024];
__device__ float g_ln[(size_t)Mv*1024];
__device__ float g_h1[(size_t)Mv*1024];
__device__ float g_kvr[(size_t)Mv*8];
__device__ float g_wt[3276800];
__device__ float g_pctx[Bv*NCv*Dv];
__device__ float g_pmc[Bv*NCv*Dv], g_pms[Bv*NCv*Dv], g_pmm[Bv*NCv*Dv];
__device__ float g_pkc[Bv*NCv*Pv*Vv], g_pks[Bv*NCv*Pv*Vv], g_pg[Bv*NCv];

// ================= weight transpose [K,N] -> [N,K] =================
__global__ void __launch_bounds__(256) transpose_kernel(
    const float* __restrict__ W, float* __restrict__ WT, int K, int N)
{
    __shared__ float t[32][33];
    int k0 = blockIdx.x * 32, n0 = blockIdx.y * 32;
    int tx = threadIdx.x & 31, ty = threadIdx.x >> 5;
#pragma unroll
    for (int i = ty; i < 32; i += 8) t[i][tx] = W[(size_t)(k0 + i) * N + n0 + tx];
    __syncthreads();
#pragma unroll
    for (int i = ty; i < 32; i += 8) WT[(size_t)(n0 + i) * K + k0 + tx] = t[tx][i];
}

// ================= tf32 mma.sync GEMM =================
// C[M,N] = epi(A[M,K] @ WT[N,K]^T + bias). grid=(N/128, M/128), 256 thr.
// epi: 0 none, 1 sigmoid*|*eptr|, 2 exact gelu, 4 +eptr residual,
//      5 sincos(tanh(v)*PI): cos->C, sin->C2
#define LDA 36
#define STAGE_F (2 * 128 * LDA)   // A + B tile floats per stage
__global__ void __launch_bounds__(256) mma_gemm(
    const float* __restrict__ A, const float* __restrict__ WT,
    const float* __restrict__ bias, float* __restrict__ C, float* __restrict__ C2,
    int K, int ldc, int epi, const float* __restrict__ eptr)
{
    extern __shared__ float sm[];
    const int tid = threadIdx.x, wid = tid >> 5, lane = tid & 31;
    const int warp_m = wid & 3, warp_n = wid >> 2;
    const int n0 = blockIdx.x * 128, m0 = blockIdx.y * 128;
    const int NK = K >> 5;
    const int lq = lane >> 2, lr = lane & 3;

    float c[2][8][4];
#pragma unroll
    for (int mi = 0; mi < 2; mi++)
#pragma unroll
        for (int j = 0; j < 8; j++)
#pragma unroll
            for (int q = 0; q < 4; q++) c[mi][j][q] = 0.f;

    auto load_tile = [&](int kt, int buf) {
        float* dst = sm + buf * STAGE_F;
        // A tile: 128 rows x 32 floats = 1024 float4; 256 thr x 4 iters
#pragma unroll
        for (int i = 0; i < 4; i++) {
            int idx = tid + i * 256;
            int row = idx >> 3, cq = idx & 7;
            cp16(smem_u32(dst + row * LDA + cq * 4),
                 A + (size_t)(m0 + row) * K + kt * 32 + cq * 4);
        }
        // B tile
#pragma unroll
        for (int i = 0; i < 4; i++) {
            int idx = tid + i * 256;
            int row = idx >> 3, cq = idx & 7;
            cp16(smem_u32(dst + 128 * LDA + row * LDA + cq * 4),
                 WT + (size_t)(n0 + row) * K + kt * 32 + cq * 4);
        }
        CP_COMMIT();
    };

    load_tile(0, 0);

    for (int kt = 0; kt < NK; kt++) {
        int buf = kt & 1;
        if (kt + 1 < NK) load_tile(kt + 1, buf ^ 1);
        if (kt + 1 < NK) { CP_WAIT1(); } else { CP_WAIT0(); }
        __syncthreads();

        const float* As = sm + buf * STAGE_F;
        const float* Bs = As + 128 * LDA;
#pragma unroll
        for (int ks = 0; ks < 4; ks++) {
            int kb = ks * 8;
            uint32_t a[2][4];
#pragma unroll
            for (int mi = 0; mi < 2; mi++) {
                int mr = warp_m * 32 + mi * 16 + lq;
                a[mi][0] = f2tf32(As[mr * LDA + kb + lr]);
                a[mi][1] = f2tf32(As[(mr + 8) * LDA + kb + lr]);
                a[mi][2] = f2tf32(As[mr * LDA + kb + 4 + lr]);
                a[mi][3] = f2tf32(As[(mr + 8) * LDA + kb + 4 + lr]);
            }
#pragma unroll
            for (int j = 0; j < 8; j++) {
                int nr = warp_n * 64 + j * 8 + lq;
                uint32_t b0 = f2tf32(Bs[nr * LDA + kb + lr]);
                uint32_t b1 = f2tf32(Bs[nr * LDA + kb + 4 + lr]);
                mma_tf32(c[0][j], a[0][0], a[0][1], a[0][2], a[0][3], b0, b1);
                mma_tf32(c[1][j], a[1][0], a[1][1], a[1][2], a[1][3], b0, b1);
            }
        }
        __syncthreads();
    }

    // ---------------- epilogue ----------------
    float scale1 = (epi == 1) ? fabsf(*eptr) : 0.f;
#pragma unroll
    for (int mi = 0; mi < 2; mi++) {
#pragma unroll
        for (int j = 0; j < 8; j++) {
            int gm = m0 + warp_m * 32 + mi * 16 + lq;
            int gn = n0 + warp_n * 64 + j * 8 + lr * 2;
            float b0 = bias[gn], b1 = bias[gn + 1];
#pragma unroll
            for (int h = 0; h < 2; h++) {
                int gmr = gm + h * 8;
                size_t oo = (size_t)gmr * ldc + gn;
                float v0 = c[mi][j][h * 2 + 0] + b0;
                float v1 = c[mi][j][h * 2 + 1] + b1;
                if (epi == 1) {
                    v0 = scale1 / (1.f + expf(-v0));
                    v1 = scale1 / (1.f + expf(-v1));
                } else if (epi == 2) {
                    v0 = 0.5f * v0 * (1.f + erff(v0 * 0.70710678118654752f));
                    v1 = 0.5f * v1 * (1.f + erff(v1 * 0.70710678118654752f));
                } else if (epi == 4) {
                    v0 += eptr[oo];
                    v1 += eptr[oo + 1];
                } else if (epi == 5) {
                    float t0 = tanhf(v0) * PI_F, t1 = tanhf(v1) * PI_F;
                    float s0, c0, s1, c1;
                    sincosf(t0, &s0, &c0);
                    sincosf(t1, &s1, &c1);
                    C[oo] = c0; C[oo + 1] = c1;
                    C2[oo] = s0; C2[oo + 1] = s1;
                    continue;
                }
                C[oo] = v0; C[oo + 1] = v1;
            }
        }
    }
}

// ================= phi sincos =================
__global__ void phi_kernel(const float* __restrict__ pos) {
    int idx = blockIdx.x * blockDim.x + threadIdx.x;
    if (idx < Lv * Dv) {
        float s, c;
        sincosf(pos[idx], &s, &c);
        g_cphi[idx] = c; g_sphi[idx] = s;
    }
}

// ================= context_avg scan =================
__global__ void ctx_p1(const float* __restrict__ x) {
    int bc = blockIdx.x; int b = bc >> 5, c = bc & 31;
    int d = blockIdx.y * 128 + threadIdx.x;
    const float* xp = x + ((size_t)(b * Lv + c * LCv)) * Dv + d;
    float s = 0.f;
    for (int i = 0; i < LCv; i++) s += xp[(size_t)i * Dv];
    g_pctx[(size_t)bc * Dv + d] = s;
}
__global__ void ctx_p2() {
    int idx = blockIdx.x * blockDim.x + threadIdx.x;
    if (idx >= Bv * Dv) return;
    int b = idx / Dv, d = idx % Dv;
    float run = 0.f;
    for (int c = 0; c < NCv; c++) {
        size_t o = ((size_t)(b * NCv + c)) * Dv + d;
        float t = g_pctx[o]; g_pctx[o] = run; run += t;
    }
}
__global__ void ctx_p3(const float* __restrict__ x) {
    int bc = blockIdx.x; int b = bc >> 5, c = bc & 31;
    int d = blockIdx.y * 128 + threadIdx.x;
    const float* xp = x + ((size_t)(b * Lv + c * LCv)) * Dv + d;
    float s = g_pctx[(size_t)bc * Dv + d];
    for (int i = 0; i < LCv; i++) {
        int l = c * LCv + i;
        float xv = xp[(size_t)i * Dv];
        s += xv;
        size_t row = (size_t)(b * Lv + l);
        g_xcat[row * 1024 + d] = xv;
        g_xcat[row * 1024 + 512 + d] = s / (float)(l + 1);
    }
}

// ================= values*gate (N=8 + N=1) =================
__global__ void __launch_bounds__(256) vg_kernel(
    const float* __restrict__ x, const float* __restrict__ w_ve,
    const float* __restrict__ b_ve, const float* __restrict__ w_g,
    const float* __restrict__ b_g)
{
    __shared__ float sw[8 * 512];
    __shared__ float sg[512];
    int tid = threadIdx.x;
    for (int idx = tid; idx < 512 * 8; idx += 256) {
        int k = idx >> 3, v = idx & 7;
        sw[v * 512 + k] = w_ve[idx];
    }
    for (int idx = tid; idx < 512; idx += 256) sg[idx] = w_g[idx];
    __syncthreads();
    int lane = tid & 31, w = tid >> 5;
    int m = blockIdx.x * 8 + w;
    const float* xr = x + (size_t)m * 512;
    float acc[8] = {0, 0, 0, 0, 0, 0, 0, 0}, ag = 0.f;
    for (int j = 0; j < 16; j++) {
        int k = lane + 32 * j;
        float xk = xr[k];
#pragma unroll
        for (int v = 0; v < 8; v++) acc[v] += xk * sw[v * 512 + k];
        ag += xk * sg[k];
    }
#pragma unroll
    for (int o = 16; o; o >>= 1) {
#pragma unroll
        for (int v = 0; v < 8; v++) acc[v] += __shfl_xor_sync(0xffffffffu, acc[v], o);
        ag += __shfl_xor_sync(0xffffffffu, ag, o);
    }
    if (lane == 0) {
        float gate = 1.f / (1.f + expf(-(ag + b_g[0])));
        g_gate[m] = gate;
#pragma unroll
        for (int v = 0; v < 8; v++) g_gv[(size_t)m * 8 + v] = (acc[v] + b_ve[v]) * gate;
    }
}

// ================= mem1 scan + fused pos_ret =================
__global__ void mem1_p1() {
    int bc = blockIdx.x; int b = bc >> 5, c = bc & 31;
    int d = blockIdx.y * 128 + threadIdx.x;
    size_t base = ((size_t)(b * Lv + c * LCv)) * Dv + d;
    float sc = 0.f, ss = 0.f, sm = 0.f;
    for (int i = 0; i < LCv; i++) {
        int lg = c * LCv + i;
        float mag = g_mag[base + (size_t)i * Dv];
        float v1  = g_v1[base + (size_t)i * Dv];
        float w = mag * v1;
        size_t pidx = (size_t)lg * Dv + d;
        sc += w * g_cphi[pidx];
        ss += w * g_sphi[pidx];
        sm += mag;
    }
    size_t o = (size_t)bc * Dv + d;
    g_pmc[o] = sc; g_pms[o] = ss; g_pmm[o] = sm;
}
__global__ void mem1_p2() {
    int idx = blockIdx.x * blockDim.x + threadIdx.x;
    if (idx >= Bv * Dv) return;
    int b = idx / Dv, d = idx % Dv;
    float r1 = 0.f, r2 = 0.f, r3 = 0.f;
    for (int c = 0; c < NCv; c++) {
        size_t o = ((size_t)(b * NCv + c)) * Dv + d;
        float t1 = g_pmc[o]; g_pmc[o] = r1; r1 += t1;
        float t2 = g_pms[o]; g_pms[o] = r2; r2 += t2;
        float t3 = g_pmm[o]; g_pmm[o] = r3; r3 += t3;
    }
}
__global__ void mem1_p3(const float* __restrict__ pos) {
    int bc = blockIdx.x; int b = bc >> 5, c = bc & 31;
    int d = blockIdx.y * 128 + threadIdx.x;
    size_t base = ((size_t)(b * Lv + c * LCv)) * Dv + d;
    size_t po = (size_t)bc * Dv + d;
    float sc = g_pmc[po], ss = g_pms[po], sm = g_pmm[po];
    for (int i = 0; i < LCv; i++) {
        int lg = c * LCv + i;
        float mag = g_mag[base + (size_t)i * Dv];
        float v1  = g_v1[base + (size_t)i * Dv];
        float w = mag * v1;
        size_t pidx = (size_t)lg * Dv + d;
        sc += w * g_cphi[pidx];
        ss += w * g_sphi[pidx];
        sm += mag;
        float ph = pos[pidx] + g_qd[base + (size_t)i * Dv];
        float sq, cq;
        sincosf(ph, &sq, &cq);
        g_posret[base + (size_t)i * Dv] =
            (sc * cq + ss * sq) * rsqrtf(sm + 1e-8f) * INV_SQRT_D;
    }
}

// ================= kv phasor scan + retrieval =================
__global__ void __launch_bounds__(256) kv_p1() {
    __shared__ float s_csp[128], s_ssp[128], s_gv[8];
    int bc = blockIdx.x; int b = bc >> 5, c = bc & 31;
    int tid = threadIdx.x;
    int v = tid & 7, p_base = (tid >> 3) * 4;
    float aC[4] = {0, 0, 0, 0}, aS[4] = {0, 0, 0, 0};
    float gs = 0.f;
    for (int i = 0; i < LCv; i++) {
        int m = b * Lv + c * LCv + i;
        if (tid < 128) s_csp[tid] = g_csp[(size_t)m * 128 + tid];
        else           s_ssp[tid - 128] = g_ssp[(size_t)m * 128 + (tid - 128)];
        if (tid < 8) s_gv[tid] = g_gv[(size_t)m * 8 + tid];
        if (tid == 0) gs += g_gate[m];
        __syncthreads();
        float gvv = s_gv[v];
#pragma unroll
        for (int j = 0; j < 4; j++) {
            aC[j] += s_csp[p_base + j] * gvv;
            aS[j] += s_ssp[p_base + j] * gvv;
        }
        __syncthreads();
    }
#pragma unroll
    for (int j = 0; j < 4; j++) {
        size_t o = (size_t)bc * 1024 + (size_t)(p_base + j) * 8 + v;
        g_pkc[o] = aC[j]; g_pks[o] = aS[j];
    }
    if (tid == 0) g_pg[bc] = gs;
}
__global__ void kv_p2() {
    int idx = blockIdx.x * blockDim.x + threadIdx.x;
    if (idx < Bv * Pv * Vv) {
        int b = idx >> 10, pv = idx & 1023;
        float rc = 0.f, rs = 0.f;
        for (int c = 0; c < NCv; c++) {
            size_t o = ((size_t)(b * NCv + c)) * 1024 + pv;
            float tc = g_pkc[o]; g_pkc[o] = rc; rc += tc;
            float ts = g_pks[o]; g_pks[o] = rs; rs += ts;
        }
    }
    if (idx < Bv) {
        float rg = 0.f;
        for (int c = 0; c < NCv; c++) {
            size_t o = (size_t)idx * NCv + c;
            float t = g_pg[o]; g_pg[o] = rg; rg += t;
        }
    }
}
__global__ void __launch_bounds__(256) kv_p3() {
    __shared__ float s_csp[128], s_ssp[128], s_cqp[128], s_sqp[128], s_gv[8];
    __shared__ float s_r[64];
    __shared__ float s_inv;
    int bc = blockIdx.x; int b = bc >> 5, c = bc & 31;
    int tid = threadIdx.x;
    int v = tid & 7, p_base = (tid >> 3) * 4;
    float aC[4], aS[4];
#pragma unroll
    for (int j = 0; j < 4; j++) {
        size_t o = (size_t)bc * 1024 + (size_t)(p_base + j) * 8 + v;
        aC[j] = g_pkc[o]; aS[j] = g_pks[o];
    }
    float gsum = (tid == 0) ? g_pg[bc] : 0.f;
    for (int i = 0; i < LCv; i++) {
        int m = b * Lv + c * LCv + i;
        if (tid < 128) {
            s_csp[tid] = g_csp[(size_t)m * 128 + tid];
            s_cqp[tid] = g_cqp[(size_t)m * 128 + tid];
        } else {
            int t = tid - 128;
            s_ssp[t] = g_ssp[(size_t)m * 128 + t];
            s_sqp[t] = g_sqp[(size_t)m * 128 + t];
        }
        if (tid < 8) s_gv[tid] = g_gv[(size_t)m * 8 + tid];
        if (tid == 0) {
            gsum += g_gate[m];
            s_inv = rsqrtf(fmaxf(gsum, 1.0f));
        }
        __syncthreads();
        float gvv = s_gv[v];
        float pr = 0.f;
#pragma unroll
        for (int j = 0; j < 4; j++) {
            int p = p_base + j;
            aC[j] += s_csp[p] * gvv;
            aS[j] += s_ssp[p] * gvv;
            pr += s_cqp[p] * aC[j] + s_sqp[p] * aS[j];
        }
        pr += __shfl_xor_sync(0xffffffffu, pr, 8);
        pr += __shfl_xor_sync(0xffffffffu, pr, 16);
        if ((tid & 31) < 8) s_r[(tid >> 5) * 8 + (tid & 7)] = pr;
        __syncthreads();
        if (tid < 8) {
            float accv = 0.f;
#pragma unroll
            for (int w = 0; w < 8; w++) accv += s_r[w * 8 + tid];
            g_kvr[(size_t)m * 8 + tid] = accv * s_inv * INV_SQRT_P;
        }
        __syncthreads();
    }
}

// ================= kv_out (K=8) =================
__global__ void __launch_bounds__(256) kvout_kernel(
    const float* __restrict__ w_kv, const float* __restrict__ b_kv)
{
    int tid = threadIdx.x;
    float wk0[8], wk1[8];
#pragma unroll
    for (int k = 0; k < 8; k++) {
        wk0[k] = w_kv[k * 512 + tid];
        wk1[k] = w_kv[k * 512 + tid + 256];
    }
    float bb0 = b_kv[tid], bb1 = b_kv[tid + 256];
    int m0 = blockIdx.x * 32;
    for (int r = 0; r < 32; r++) {
        int m = m0 + r;
        const float* kv = g_kvr + (size_t)m * 8;
        float o0 = bb0, o1 = bb1;
#pragma unroll
        for (int k = 0; k < 8; k++) {
            float kvk = __ldg(&kv[k]);
            o0 += kvk * wk0[k];
            o1 += kvk * wk1[k];
        }
        g_ccat[(size_t)m * 1024 + 512 + tid] = o0;
        g_ccat[(size_t)m * 1024 + 768 + tid] = o1;
    }
}

// ================= LayerNorm =================
__global__ void __launch_bounds__(256) ln_kernel(
    const float* __restrict__ lng, const float* __restrict__ lnb)
{
    int m = blockIdx.x, tid = threadIdx.x;
    const float4* row = (const float4*)(g_ccat + (size_t)m * 1024);
    float4 val = row[tid];
    float s = val.x + val.y + val.z + val.w;
    float q = val.x * val.x + val.y * val.y + val.z * val.z + val.w * val.w;
#pragma unroll
    for (int o = 16; o; o >>= 1) {
        s += __shfl_xor_sync(0xffffffffu, s, o);
        q += __shfl_xor_sync(0xffffffffu, q, o);
    }
    __shared__ float ss[8], sq[8];
    __shared__ float smu, srs;
    if ((tid & 31) == 0) { ss[tid >> 5] = s; sq[tid >> 5] = q; }
    __syncthreads();
    if (tid == 0) {
        float S = 0.f, Q = 0.f;
#pragma unroll
        for (int w = 0; w < 8; w++) { S += ss[w]; Q += sq[w]; }
        float mu = S * (1.f / 1024.f);
        float var = Q * (1.f / 1024.f) - mu * mu;
        smu = mu; srs = rsqrtf(var + 1e-5f);
    }
    __syncthreads();
    float mu = smu, rs = srs;
    float4 g4 = ((const float4*)lng)[tid];
    float4 b4 = ((const float4*)lnb)[tid];
    float4 o;
    o.x = (val.x - mu) * rs * g4.x + b4.x;
    o.y = (val.y - mu) * rs * g4.y + b4.y;
    o.z = (val.z - mu) * rs * g4.z + b4.z;
    o.w = (val.w - mu) * rs * g4.w + b4.w;
    ((float4*)(g_ln + (size_t)m * 1024))[tid] = o;
}

// ================= launch =================
extern "C" void kernel_launch(void* const* d_in, const int* in_sizes, int n_in,
                              void* d_out, int out_size)
{
    const float* x    = (const float*)d_in[0];
    const float* pos  = (const float*)d_in[1];
    const float* ms   = (const float*)d_in[2];
    const float* w_v  = (const float*)d_in[3];
    const float* b_v  = (const float*)d_in[4];
    const float* w_o  = (const float*)d_in[5];
    const float* b_o  = (const float*)d_in[6];
    const float* w_m  = (const float*)d_in[7];
    const float* b_m  = (const float*)d_in[8];
    const float* w_q  = (const float*)d_in[9];
    const float* b_q  = (const float*)d_in[10];
    const float* w_ke = (const float*)d_in[11];
    const float* b_ke = (const float*)d_in[12];
    const float* w_ve = (const float*)d_in[13];
    const float* b_ve = (const float*)d_in[14];
    const float* w_s1 = (const float*)d_in[15];
    const float* b_s1 = (const float*)d_in[16];
    const float* w_s2 = (const float*)d_in[17];
    const float* b_s2 = (const float*)d_in[18];
    const float* w_g  = (const float*)d_in[19];
    const float* b_g  = (const float*)d_in[20];
    const float* w_kv = (const float*)d_in[21];
    const float* b_kv = (const float*)d_in[22];
    const float* lng  = (const float*)d_in[23];
    const float* lnb  = (const float*)d_in[24];
    const float* w_t1 = (const float*)d_in[25];
    const float* b_t1 = (const float*)d_in[26];
    const float* w_t2 = (const float*)d_in[27];
    const float* b_t2 = (const float*)d_in[28];
    float* out = (float*)d_out;

    float *p_xcat, *p_v1, *p_mag, *p_qd, *p_s1g, *p_posret, *p_ccat, *p_ln,
          *p_h1, *p_wt, *p_cqp, *p_sqp, *p_csp, *p_ssp;
    cudaGetSymbolAddress((void**)&p_xcat, g_xcat);
    cudaGetSymbolAddress((void**)&p_v1, g_v1);
    cudaGetSymbolAddress((void**)&p_mag, g_mag);
    cudaGetSymbolAddress((void**)&p_qd, g_qd);
    cudaGetSymbolAddress((void**)&p_s1g, g_s1g);
    cudaGetSymbolAddress((void**)&p_posret, g_posret);
    cudaGetSymbolAddress((void**)&p_ccat, g_ccat);
    cudaGetSymbolAddress((void**)&p_ln, g_ln);
    cudaGetSymbolAddress((void**)&p_h1, g_h1);
    cudaGetSymbolAddress((void**)&p_wt, g_wt);
    cudaGetSymbolAddress((void**)&p_cqp, g_cqp);
    cudaGetSymbolAddress((void**)&p_sqp, g_sqp);
    cudaGetSymbolAddress((void**)&p_csp, g_csp);
    cudaGetSymbolAddress((void**)&p_ssp, g_ssp);

    float* wt_v  = p_wt + 0;
    float* wt_m  = p_wt + 262144;
    float* wt_q  = p_wt + 524288;
    float* wt_o  = p_wt + 786432;
    float* wt_ke = p_wt + 1048576;
    float* wt_s1 = p_wt + 1114112;
    float* wt_s2 = p_wt + 1638400;
    float* wt_t1 = p_wt + 1703936;
    float* wt_t2 = p_wt + 2752512;

    const int SMEM = 2 * STAGE_F * 4;  // 73728 B
    cudaFuncSetAttribute(mma_gemm, cudaFuncAttributeMaxDynamicSharedMemorySize, SMEM);

    dim3 tb(256);
    transpose_kernel<<<dim3(16, 16), 256>>>(w_v, wt_v, 512, 512);
    transpose_kernel<<<dim3(16, 16), 256>>>(w_m, wt_m, 512, 512);
    transpose_kernel<<<dim3(16, 16), 256>>>(w_q, wt_q, 512, 512);
    transpose_kernel<<<dim3(16, 16), 256>>>(w_o, wt_o, 512, 512);
    transpose_kernel<<<dim3(16, 4), 256>>>(w_ke, wt_ke, 512, 128);
    transpose_kernel<<<dim3(32, 16), 256>>>(w_s1, wt_s1, 1024, 512);
    transpose_kernel<<<dim3(16, 4), 256>>>(w_s2, wt_s2, 512, 128);
    transpose_kernel<<<dim3(32, 32), 256>>>(w_t1, wt_t1, 1024, 1024);
    transpose_kernel<<<dim3(32, 16), 256>>>(w_t2, wt_t2, 1024, 512);

    dim3 gScan(Bv * NCv, Dv / 128);

    phi_kernel<<<(Lv * Dv + 255) / 256, 256>>>(pos);
    ctx_p1<<<gScan, 128>>>(x);
    ctx_p2<<<(Bv * Dv + 255) / 256, 256>>>();
    ctx_p3<<<gScan, 128>>>(x);

    // projections (tf32 mma.sync)
    mma_gemm<<<dim3(4, 128), tb, SMEM>>>(x, wt_v, b_v, p_v1, nullptr, 512, 512, 0, nullptr);
    mma_gemm<<<dim3(4, 128), tb, SMEM>>>(x, wt_m, b_m, p_mag, nullptr, 512, 512, 1, ms);
    mma_gemm<<<dim3(4, 128), tb, SMEM>>>(x, wt_q, b_q, p_qd, nullptr, 512, 512, 0, nullptr);
    mma_gemm<<<dim3(1, 128), tb, SMEM>>>(x, wt_ke, b_ke, p_cqp, p_sqp, 512, 128, 5, nullptr);
    vg_kernel<<<Mv / 8, 256>>>(x, w_ve, b_ve, w_g, b_g);
    mma_gemm<<<dim3(4, 128), tb, SMEM>>>(p_xcat, wt_s1, b_s1, p_s1g, nullptr, 1024, 512, 2, nullptr);
    mma_gemm<<<dim3(1, 128), tb, SMEM>>>(p_s1g, wt_s2, b_s2, p_csp, p_ssp, 512, 128, 5, nullptr);

    // mem1 scan + pos_out
    mem1_p1<<<gScan, 128>>>();
    mem1_p2<<<(Bv * Dv + 255) / 256, 256>>>();
    mem1_p3<<<gScan, 128>>>(pos);
    mma_gemm<<<dim3(4, 128), tb, SMEM>>>(p_posret, wt_o, b_o, p_ccat, nullptr, 512, 1024, 0, nullptr);

    // kv scan + retrieval + kv_out
    kv_p1<<<Bv * NCv, 256>>>();
    kv_p2<<<(Bv * Pv * Vv + 255) / 256, 256>>>();
    kv_p3<<<Bv * NCv, 256>>>();
    kvout_kernel<<<Mv / 32, 256>>>(w_kv, b_kv);

    // LN + output MLP + residual
    ln_kernel<<<Mv, 256>>>(lng, lnb);
    mma_gemm<<<dim3(8, 128), tb, SMEM>>>(p_ln, wt_t1, b_t1, p_h1, nullptr, 1024, 1024, 2, nullptr);
    mma_gemm<<<dim3(4, 128), tb, SMEM>>>(p_h1, wt_t2, b_t2, out, nullptr, 1024, 512, 4, x);
}

// round 5
// speedup vs baseline: 3.0416x; 1.2243x over previous
#include <cuda_runtime.h>
#include <math.h>
#include <stdint.h>

#define Bv 4
#define Lv 4096
#define Dv 512
#define Pv 128
#define Vv 8
#define Mv (Bv*Lv)          // 16384
#define NCv 64
#define NC_SH 6
#define NC_MASK 63
#define LCv (Lv/NCv)        // 64
#define PI_F 3.14159265358979323846f
#define INV_SQRT_D 0.044194173824159216f
#define INV_SQRT_P 0.08838834764831845f

// ================= helpers =================
__device__ __forceinline__ uint32_t smem_u32(const void* p) {
    uint32_t a;
    asm("{ .reg .u64 t; cvta.to.shared.u64 t, %1; cvt.u32.u64 %0, t; }" : "=r"(a) : "l"(p));
    return a;
}
__device__ __forceinline__ void cp16(uint32_t s, const void* g) {
    asm volatile("cp.async.cg.shared.global [%0], [%1], 16;" :: "r"(s), "l"(g) : "memory");
}
#define CP_COMMIT() asm volatile("cp.async.commit_group;" ::: "memory")
#define CP_WAIT1()  asm volatile("cp.async.wait_group 1;" ::: "memory")
#define CP_WAIT0()  asm volatile("cp.async.wait_group 0;" ::: "memory")

__device__ __forceinline__ float f2tf32f(float v) {
    uint32_t u;
    asm("cvt.rna.tf32.f32 %0, %1;" : "=r"(u) : "f"(v));
    return __uint_as_float(u);
}
__device__ __forceinline__ void mma_tf32(float* c,
    uint32_t a0, uint32_t a1, uint32_t a2, uint32_t a3,
    uint32_t b0, uint32_t b1)
{
    asm volatile(
        "mma.sync.aligned.m16n8k8.row.col.f32.tf32.tf32.f32 "
        "{%0,%1,%2,%3}, {%4,%5,%6,%7}, {%8,%9}, {%0,%1,%2,%3};"
        : "+f"(c[0]), "+f"(c[1]), "+f"(c[2]), "+f"(c[3])
        : "r"(a0), "r"(a1), "r"(a2), "r"(a3), "r"(b0), "r"(b1));
}

// ================= scratch =================
__device__ float g_xcat[(size_t)Mv*1024];
__device__ float g_v1[(size_t)Mv*512];
__device__ float g_mag[(size_t)Mv*512];
__device__ float g_qd[(size_t)Mv*512];
__device__ float g_cqp[(size_t)Mv*128], g_sqp[(size_t)Mv*128];
__device__ float g_csp[(size_t)Mv*128], g_ssp[(size_t)Mv*128];
__device__ float g_gv[(size_t)Mv*8], g_gate[Mv];
__device__ float g_s1g[(size_t)Mv*512];
__device__ float g_cphi[(size_t)Lv*Dv], g_sphi[(size_t)Lv*Dv];
__device__ float g_posret[(size_t)Mv*512];
__device__ float g_ccat[(size_t)Mv*1024];
__device__ float g_ln[(size_t)Mv*1024];
__device__ float g_h1[(size_t)Mv*1024];
__device__ float g_kvr[(size_t)Mv*8];
__device__ float g_wt[3276800];
__device__ float g_bcat[1664];
__device__ float g_pctx[Bv*NCv*Dv];
__device__ float g_pmc[Bv*NCv*Dv], g_pms[Bv*NCv*Dv], g_pmm[Bv*NCv*Dv];
__device__ float g_pkc[Bv*NCv*Pv*Vv], g_pks[Bv*NCv*Pv*Vv], g_pg[Bv*NCv];

// arena offsets (floats)
#define WT_PROJ 0
#define WT_O    851968
#define WT_S1   1114112
#define WT_S2   1638400
#define WT_T1   1703936
#define WT_T2   2752512

// ================= batched transpose+tf32-round =================
struct TTable {
    const float* src[9];
    float* dst[9];
    int K[9], N[9], t0[9];
};
__global__ void __launch_bounds__(256) transpose_all(TTable tt) {
    __shared__ float t[32][33];
    int bid = blockIdx.x;
    int w = 8;
#pragma unroll
    for (int i = 8; i >= 0; i--) if (bid >= tt.t0[i]) { w = i; break; }
    int tl = bid - tt.t0[w];
    int K = tt.K[w], N = tt.N[w];
    int tilesK = K >> 5;
    int k0 = (tl % tilesK) * 32, n0 = (tl / tilesK) * 32;
    const float* W = tt.src[w];
    float* WT = tt.dst[w];
    int tx = threadIdx.x & 31, ty = threadIdx.x >> 5;
#pragma unroll
    for (int i = ty; i < 32; i += 8) t[i][tx] = W[(size_t)(k0 + i) * N + n0 + tx];
    __syncthreads();
#pragma unroll
    for (int i = ty; i < 32; i += 8)
        WT[(size_t)(n0 + i) * K + k0 + tx] = f2tf32f(t[tx][i]);
}

// ================= bias concat =================
__global__ void bias_concat(const float* b_v, const float* b_m,
                            const float* b_q, const float* b_ke) {
    int i = blockIdx.x * blockDim.x + threadIdx.x;
    if (i < 512)        g_bcat[i] = b_v[i];
    else if (i < 1024)  g_bcat[i] = b_m[i - 512];
    else if (i < 1536)  g_bcat[i] = b_q[i - 1024];
    else if (i < 1664)  g_bcat[i] = b_ke[i - 1536];
}

// ================= tf32 mma.sync GEMM =================
// epi: 0 none, 1 sigmoid*|*eptr|, 2 exact gelu, 4 +eptr residual,
//      5 sincos(tanh*PI)->C,C2, 6 merged-proj (v1|mag|qd|ke-sincos)
#define LDA 36
#define STAGE_F (2 * 128 * LDA)
__global__ void __launch_bounds__(256, 2) mma_gemm(
    const float* __restrict__ A, const float* __restrict__ WT,
    const float* __restrict__ bias,
    float* __restrict__ C, float* __restrict__ C2, float* __restrict__ C3,
    float* __restrict__ C4, float* __restrict__ C5,
    int K, int ldc, int epi, const float* __restrict__ eptr)
{
    extern __shared__ float sm[];
    const int tid = threadIdx.x, wid = tid >> 5, lane = tid & 31;
    const int warp_m = wid & 3, warp_n = wid >> 2;
    const int n0 = blockIdx.x * 128, m0 = blockIdx.y * 128;
    const int NK = K >> 5;
    const int lq = lane >> 2, lr = lane & 3;

    float c[2][8][4];
#pragma unroll
    for (int mi = 0; mi < 2; mi++)
#pragma unroll
        for (int j = 0; j < 8; j++)
#pragma unroll
            for (int q = 0; q < 4; q++) c[mi][j][q] = 0.f;

    auto load_tile = [&](int kt, int buf) {
        float* dst = sm + buf * STAGE_F;
#pragma unroll
        for (int i = 0; i < 4; i++) {
            int idx = tid + i * 256;
            int row = idx >> 3, cq = idx & 7;
            cp16(smem_u32(dst + row * LDA + cq * 4),
                 A + (size_t)(m0 + row) * K + kt * 32 + cq * 4);
        }
#pragma unroll
        for (int i = 0; i < 4; i++) {
            int idx = tid + i * 256;
            int row = idx >> 3, cq = idx & 7;
            cp16(smem_u32(dst + 128 * LDA + row * LDA + cq * 4),
                 WT + (size_t)(n0 + row) * K + kt * 32 + cq * 4);
        }
        CP_COMMIT();
    };

    load_tile(0, 0);

    for (int kt = 0; kt < NK; kt++) {
        int buf = kt & 1;
        if (kt + 1 < NK) load_tile(kt + 1, buf ^ 1);
        if (kt + 1 < NK) { CP_WAIT1(); } else { CP_WAIT0(); }
        __syncthreads();

        const uint32_t* As = (const uint32_t*)(sm + buf * STAGE_F);
        const uint32_t* Bs = As + 128 * LDA;
#pragma unroll
        for (int ks = 0; ks < 4; ks++) {
            int kb = ks * 8;
            uint32_t a[2][4];
#pragma unroll
            for (int mi = 0; mi < 2; mi++) {
                int mr = warp_m * 32 + mi * 16 + lq;
                a[mi][0] = As[mr * LDA + kb + lr];
                a[mi][1] = As[(mr + 8) * LDA + kb + lr];
                a[mi][2] = As[mr * LDA + kb + 4 + lr];
                a[mi][3] = As[(mr + 8) * LDA + kb + 4 + lr];
            }
#pragma unroll
            for (int j = 0; j < 8; j++) {
                int nr = warp_n * 64 + j * 8 + lq;
                uint32_t b0 = Bs[nr * LDA + kb + lr];
                uint32_t b1 = Bs[nr * LDA + kb + 4 + lr];
                mma_tf32(c[0][j], a[0][0], a[0][1], a[0][2], a[0][3], b0, b1);
                mma_tf32(c[1][j], a[1][0], a[1][1], a[1][2], a[1][3], b0, b1);
            }
        }
        __syncthreads();
    }

    // ---------------- epilogue ----------------
    float scale1 = (epi == 1 || epi == 6) ? fabsf(*eptr) : 0.f;
    int seg = n0 >> 9;   // for epi6; uniform per CTA
#pragma unroll
    for (int mi = 0; mi < 2; mi++) {
#pragma unroll
        for (int j = 0; j < 8; j++) {
            int gm = m0 + warp_m * 32 + mi * 16 + lq;
            int gn = n0 + warp_n * 64 + j * 8 + lr * 2;
            float b0 = bias[gn], b1 = bias[gn + 1];
#pragma unroll
            for (int h = 0; h < 2; h++) {
                int gmr = gm + h * 8;
                float v0 = c[mi][j][h * 2 + 0] + b0;
                float v1 = c[mi][j][h * 2 + 1] + b1;
                if (epi == 6) {
                    if (seg == 0) {
                        C[(size_t)gmr * 512 + gn] = v0;
                        C[(size_t)gmr * 512 + gn + 1] = v1;
                    } else if (seg == 1) {
                        size_t oo = (size_t)gmr * 512 + gn - 512;
                        C2[oo]     = scale1 / (1.f + expf(-v0));
                        C2[oo + 1] = scale1 / (1.f + expf(-v1));
                    } else if (seg == 2) {
                        size_t oo = (size_t)gmr * 512 + gn - 1024;
                        C3[oo] = v0; C3[oo + 1] = v1;
                    } else {
                        size_t oo = (size_t)gmr * 128 + gn - 1536;
                        float t0 = tanhf(v0) * PI_F, t1 = tanhf(v1) * PI_F;
                        float s0, cc0, s1, cc1;
                        sincosf(t0, &s0, &cc0);
                        sincosf(t1, &s1, &cc1);
                        C4[oo] = cc0; C4[oo + 1] = cc1;
                        C5[oo] = s0;  C5[oo + 1] = s1;
                    }
                    continue;
                }
                size_t oo = (size_t)gmr * ldc + gn;
                if (epi == 1) {
                    v0 = scale1 / (1.f + expf(-v0));
                    v1 = scale1 / (1.f + expf(-v1));
                } else if (epi == 2) {
                    v0 = 0.5f * v0 * (1.f + erff(v0 * 0.70710678118654752f));
                    v1 = 0.5f * v1 * (1.f + erff(v1 * 0.70710678118654752f));
                } else if (epi == 4) {
                    v0 += eptr[oo];
                    v1 += eptr[oo + 1];
                } else if (epi == 5) {
                    float t0 = tanhf(v0) * PI_F, t1 = tanhf(v1) * PI_F;
                    float s0, c0, s1, c1;
                    sincosf(t0, &s0, &c0);
                    sincosf(t1, &s1, &c1);
                    C[oo] = c0; C[oo + 1] = c1;
                    C2[oo] = s0; C2[oo + 1] = s1;
                    continue;
                }
                C[oo] = v0; C[oo + 1] = v1;
            }
        }
    }
}

// ================= phi sincos =================
__global__ void phi_kernel(const float* __restrict__ pos) {
    int idx = blockIdx.x * blockDim.x + threadIdx.x;
    if (idx < Lv * Dv) {
        float s, c;
        sincosf(pos[idx], &s, &c);
        g_cphi[idx] = c; g_sphi[idx] = s;
    }
}

// ================= context_avg scan =================
__global__ void ctx_p1(const float* __restrict__ x) {
    int bc = blockIdx.x; int b = bc >> NC_SH, c = bc & NC_MASK;
    int d = blockIdx.y * 128 + threadIdx.x;
    const float* xp = x + ((size_t)(b * Lv + c * LCv)) * Dv + d;
    float s = 0.f;
    for (int i = 0; i < LCv; i++) s += xp[(size_t)i * Dv];
    g_pctx[(size_t)bc * Dv + d] = s;
}
__global__ void ctx_p2() {
    int idx = blockIdx.x * blockDim.x + threadIdx.x;
    if (idx >= Bv * Dv) return;
    int b = idx / Dv, d = idx % Dv;
    float run = 0.f;
    for (int c = 0; c < NCv; c++) {
        size_t o = ((size_t)(b * NCv + c)) * Dv + d;
        float t = g_pctx[o]; g_pctx[o] = run; run += t;
    }
}
__global__ void ctx_p3(const float* __restrict__ x) {
    int bc = blockIdx.x; int b = bc >> NC_SH, c = bc & NC_MASK;
    int d = blockIdx.y * 128 + threadIdx.x;
    const float* xp = x + ((size_t)(b * Lv + c * LCv)) * Dv + d;
    float s = g_pctx[(size_t)bc * Dv + d];
    for (int i = 0; i < LCv; i++) {
        int l = c * LCv + i;
        float xv = xp[(size_t)i * Dv];
        s += xv;
        size_t row = (size_t)(b * Lv + l);
        g_xcat[row * 1024 + d] = xv;
        g_xcat[row * 1024 + 512 + d] = s / (float)(l + 1);
    }
}

// ================= values*gate =================
__global__ void __launch_bounds__(256) vg_kernel(
    const float* __restrict__ x, const float* __restrict__ w_ve,
    const float* __restrict__ b_ve, const float* __restrict__ w_g,
    const float* __restrict__ b_g)
{
    __shared__ float sw[8 * 512];
    __shared__ float sg[512];
    int tid = threadIdx.x;
    for (int idx = tid; idx < 512 * 8; idx += 256) {
        int k = idx >> 3, v = idx & 7;
        sw[v * 512 + k] = w_ve[idx];
    }
    for (int idx = tid; idx < 512; idx += 256) sg[idx] = w_g[idx];
    __syncthreads();
    int lane = tid & 31, w = tid >> 5;
    int m = blockIdx.x * 8 + w;
    const float* xr = x + (size_t)m * 512;
    float acc[8] = {0, 0, 0, 0, 0, 0, 0, 0}, ag = 0.f;
    for (int j = 0; j < 16; j++) {
        int k = lane + 32 * j;
        float xk = xr[k];
#pragma unroll
        for (int v = 0; v < 8; v++) acc[v] += xk * sw[v * 512 + k];
        ag += xk * sg[k];
    }
#pragma unroll
    for (int o = 16; o; o >>= 1) {
#pragma unroll
        for (int v = 0; v < 8; v++) acc[v] += __shfl_xor_sync(0xffffffffu, acc[v], o);
        ag += __shfl_xor_sync(0xffffffffu, ag, o);
    }
    if (lane == 0) {
        float gate = 1.f / (1.f + expf(-(ag + b_g[0])));
        g_gate[m] = gate;
#pragma unroll
        for (int v = 0; v < 8; v++) g_gv[(size_t)m * 8 + v] = (acc[v] + b_ve[v]) * gate;
    }
}

// ================= mem1 scan + fused pos_ret =================
__global__ void mem1_p1() {
    int bc = blockIdx.x; int b = bc >> NC_SH, c = bc & NC_MASK;
    int d = blockIdx.y * 128 + threadIdx.x;
    size_t base = ((size_t)(b * Lv + c * LCv)) * Dv + d;
    float sc = 0.f, ss = 0.f, sm = 0.f;
    for (int i = 0; i < LCv; i++) {
        int lg = c * LCv + i;
        float mag = g_mag[base + (size_t)i * Dv];
        float v1  = g_v1[base + (size_t)i * Dv];
        float w = mag * v1;
        size_t pidx = (size_t)lg * Dv + d;
        sc += w * g_cphi[pidx];
        ss += w * g_sphi[pidx];
        sm += mag;
    }
    size_t o = (size_t)bc * Dv + d;
    g_pmc[o] = sc; g_pms[o] = ss; g_pmm[o] = sm;
}
__global__ void mem1_p2() {
    int idx = blockIdx.x * blockDim.x + threadIdx.x;
    if (idx >= Bv * Dv) return;
    int b = idx / Dv, d = idx % Dv;
    float r1 = 0.f, r2 = 0.f, r3 = 0.f;
    for (int c = 0; c < NCv; c++) {
        size_t o = ((size_t)(b * NCv + c)) * Dv + d;
        float t1 = g_pmc[o]; g_pmc[o] = r1; r1 += t1;
        float t2 = g_pms[o]; g_pms[o] = r2; r2 += t2;
        float t3 = g_pmm[o]; g_pmm[o] = r3; r3 += t3;
    }
}
__global__ void mem1_p3(const float* __restrict__ pos) {
    int bc = blockIdx.x; int b = bc >> NC_SH, c = bc & NC_MASK;
    int d = blockIdx.y * 128 + threadIdx.x;
    size_t base = ((size_t)(b * Lv + c * LCv)) * Dv + d;
    size_t po = (size_t)bc * Dv + d;
    float sc = g_pmc[po], ss = g_pms[po], sm = g_pmm[po];
    for (int i = 0; i < LCv; i++) {
        int lg = c * LCv + i;
        float mag = g_mag[base + (size_t)i * Dv];
        float v1  = g_v1[base + (size_t)i * Dv];
        float w = mag * v1;
        size_t pidx = (size_t)lg * Dv + d;
        sc += w * g_cphi[pidx];
        ss += w * g_sphi[pidx];
        sm += mag;
        float ph = pos[pidx] + g_qd[base + (size_t)i * Dv];
        float sq, cq;
        sincosf(ph, &sq, &cq);
        g_posret[base + (size_t)i * Dv] =
            (sc * cq + ss * sq) * rsqrtf(sm + 1e-8f) * INV_SQRT_D;
    }
}

// ================= kv phasor scan + retrieval =================
__global__ void __launch_bounds__(256) kv_p1() {
    __shared__ float s_csp[128], s_ssp[128], s_gv[8];
    int bc = blockIdx.x; int b = bc >> NC_SH, c = bc & NC_MASK;
    int tid = threadIdx.x;
    int v = tid & 7, p_base = (tid >> 3) * 4;
    float aC[4] = {0, 0, 0, 0}, aS[4] = {0, 0, 0, 0};
    float gs = 0.f;
    for (int i = 0; i < LCv; i++) {
        int m = b * Lv + c * LCv + i;
        if (tid < 128) s_csp[tid] = g_csp[(size_t)m * 128 + tid];
        else           s_ssp[tid - 128] = g_ssp[(size_t)m * 128 + (tid - 128)];
        if (tid < 8) s_gv[tid] = g_gv[(size_t)m * 8 + tid];
        if (tid == 0) gs += g_gate[m];
        __syncthreads();
        float gvv = s_gv[v];
#pragma unroll
        for (int j = 0; j < 4; j++) {
            aC[j] += s_csp[p_base + j] * gvv;
            aS[j] += s_ssp[p_base + j] * gvv;
        }
        __syncthreads();
    }
#pragma unroll
    for (int j = 0; j < 4; j++) {
        size_t o = (size_t)bc * 1024 + (size_t)(p_base + j) * 8 + v;
        g_pkc[o] = aC[j]; g_pks[o] = aS[j];
    }
    if (tid == 0) g_pg[bc] = gs;
}
__global__ void kv_p2() {
    int idx = blockIdx.x * blockDim.x + threadIdx.x;
    if (idx < Bv * Pv * Vv) {
        int b = idx >> 10, pv = idx & 1023;
        float rc = 0.f, rs = 0.f;
        for (int c = 0; c < NCv; c++) {
            size_t o = ((size_t)(b * NCv + c)) * 1024 + pv;
            float tc = g_pkc[o]; g_pkc[o] = rc; rc += tc;
            float ts = g_pks[o]; g_pks[o] = rs; rs += ts;
        }
    }
    if (idx < Bv) {
        float rg = 0.f;
        for (int c = 0; c < NCv; c++) {
            size_t o = (size_t)idx * NCv + c;
            float t = g_pg[o]; g_pg[o] = rg; rg += t;
        }
    }
}
__global__ void __launch_bounds__(256) kv_p3() {
    __shared__ float s_csp[128], s_ssp[128], s_cqp[128], s_sqp[128], s_gv[8];
    __shared__ float s_r[64];
    __shared__ float s_inv;
    int bc = blockIdx.x; int b = bc >> NC_SH, c = bc & NC_MASK;
    int tid = threadIdx.x;
    int v = tid & 7, p_base = (tid >> 3) * 4;
    float aC[4], aS[4];
#pragma unroll
    for (int j = 0; j < 4; j++) {
        size_t o = (size_t)bc * 1024 + (size_t)(p_base + j) * 8 + v;
        aC[j] = g_pkc[o]; aS[j] = g_pks[o];
    }
    float gsum = (tid == 0) ? g_pg[bc] : 0.f;
    for (int i = 0; i < LCv; i++) {
        int m = b * Lv + c * LCv + i;
        if (tid < 128) {
            s_csp[tid] = g_csp[(size_t)m * 128 + tid];
            s_cqp[tid] = g_cqp[(size_t)m * 128 + tid];
        } else {
            int t = tid - 128;
            s_ssp[t] = g_ssp[(size_t)m * 128 + t];
            s_sqp[t] = g_sqp[(size_t)m * 128 + t];
        }
        if (tid < 8) s_gv[tid] = g_gv[(size_t)m * 8 + tid];
        if (tid == 0) {
            gsum += g_gate[m];
            s_inv = rsqrtf(fmaxf(gsum, 1.0f));
        }
        __syncthreads();
        float gvv = s_gv[v];
        float pr = 0.f;
#pragma unroll
        for (int j = 0; j < 4; j++) {
            int p = p_base + j;
            aC[j] += s_csp[p] * gvv;
            aS[j] += s_ssp[p] * gvv;
            pr += s_cqp[p] * aC[j] + s_sqp[p] * aS[j];
        }
        pr += __shfl_xor_sync(0xffffffffu, pr, 8);
        pr += __shfl_xor_sync(0xffffffffu, pr, 16);
        if ((tid & 31) < 8) s_r[(tid >> 5) * 8 + (tid & 7)] = pr;
        __syncthreads();
        if (tid < 8) {
            float accv = 0.f;
#pragma unroll
            for (int w = 0; w < 8; w++) accv += s_r[w * 8 + tid];
            g_kvr[(size_t)m * 8 + tid] = accv * s_inv * INV_SQRT_P;
        }
        __syncthreads();
    }
}

// ================= kv_out (K=8) =================
__global__ void __launch_bounds__(256) kvout_kernel(
    const float* __restrict__ w_kv, const float* __restrict__ b_kv)
{
    int tid = threadIdx.x;
    float wk0[8], wk1[8];
#pragma unroll
    for (int k = 0; k < 8; k++) {
        wk0[k] = w_kv[k * 512 + tid];
        wk1[k] = w_kv[k * 512 + tid + 256];
    }
    float bb0 = b_kv[tid], bb1 = b_kv[tid + 256];
    int m0 = blockIdx.x * 32;
    for (int r = 0; r < 32; r++) {
        int m = m0 + r;
        const float* kv = g_kvr + (size_t)m * 8;
        float o0 = bb0, o1 = bb1;
#pragma unroll
        for (int k = 0; k < 8; k++) {
            float kvk = __ldg(&kv[k]);
            o0 += kvk * wk0[k];
            o1 += kvk * wk1[k];
        }
        g_ccat[(size_t)m * 1024 + 512 + tid] = o0;
        g_ccat[(size_t)m * 1024 + 768 + tid] = o1;
    }
}

// ================= LayerNorm =================
__global__ void __launch_bounds__(256) ln_kernel(
    const float* __restrict__ lng, const float* __restrict__ lnb)
{
    int m = blockIdx.x, tid = threadIdx.x;
    const float4* row = (const float4*)(g_ccat + (size_t)m * 1024);
    float4 val = row[tid];
    float s = val.x + val.y + val.z + val.w;
    float q = val.x * val.x + val.y * val.y + val.z * val.z + val.w * val.w;
#pragma unroll
    for (int o = 16; o; o >>= 1) {
        s += __shfl_xor_sync(0xffffffffu, s, o);
        q += __shfl_xor_sync(0xffffffffu, q, o);
    }
    __shared__ float ss[8], sq[8];
    __shared__ float smu, srs;
    if ((tid & 31) == 0) { ss[tid >> 5] = s; sq[tid >> 5] = q; }
    __syncthreads();
    if (tid == 0) {
        float S = 0.f, Q = 0.f;
#pragma unroll
        for (int w = 0; w < 8; w++) { S += ss[w]; Q += sq[w]; }
        float mu = S * (1.f / 1024.f);
        float var = Q * (1.f / 1024.f) - mu * mu;
        smu = mu; srs = rsqrtf(var + 1e-5f);
    }
    __syncthreads();
    float mu = smu, rs = srs;
    float4 g4 = ((const float4*)lng)[tid];
    float4 b4 = ((const float4*)lnb)[tid];
    float4 o;
    o.x = (val.x - mu) * rs * g4.x + b4.x;
    o.y = (val.y - mu) * rs * g4.y + b4.y;
    o.z = (val.z - mu) * rs * g4.z + b4.z;
    o.w = (val.w - mu) * rs * g4.w + b4.w;
    ((float4*)(g_ln + (size_t)m * 1024))[tid] = o;
}

// ================= launch =================
extern "C" void kernel_launch(void* const* d_in, const int* in_sizes, int n_in,
                              void* d_out, int out_size)
{
    const float* x    = (const float*)d_in[0];
    const float* pos  = (const float*)d_in[1];
    const float* ms   = (const float*)d_in[2];
    const float* w_v  = (const float*)d_in[3];
    const float* b_v  = (const float*)d_in[4];
    const float* w_o  = (const float*)d_in[5];
    const float* b_o  = (const float*)d_in[6];
    const float* w_m  = (const float*)d_in[7];
    const float* b_m  = (const float*)d_in[8];
    const float* w_q  = (const float*)d_in[9];
    const float* b_q  = (const float*)d_in[10];
    const float* w_ke = (const float*)d_in[11];
    const float* b_ke = (const float*)d_in[12];
    const float* w_ve = (const float*)d_in[13];
    const float* b_ve = (const float*)d_in[14];
    const float* w_s1 = (const float*)d_in[15];
    const float* b_s1 = (const float*)d_in[16];
    const float* w_s2 = (const float*)d_in[17];
    const float* b_s2 = (const float*)d_in[18];
    const float* w_g  = (const float*)d_in[19];
    const float* b_g  = (const float*)d_in[20];
    const float* w_kv = (const float*)d_in[21];
    const float* b_kv = (const float*)d_in[22];
    const float* lng  = (const float*)d_in[23];
    const float* lnb  = (const float*)d_in[24];
    const float* w_t1 = (const float*)d_in[25];
    const float* b_t1 = (const float*)d_in[26];
    const float* w_t2 = (const float*)d_in[27];
    const float* b_t2 = (const float*)d_in[28];
    float* out = (float*)d_out;

    float *p_xcat, *p_v1, *p_mag, *p_qd, *p_s1g, *p_posret, *p_ccat, *p_ln,
          *p_h1, *p_wt, *p_cqp, *p_sqp, *p_csp, *p_ssp, *p_bcat;
    cudaGetSymbolAddress((void**)&p_xcat, g_xcat);
    cudaGetSymbolAddress((void**)&p_v1, g_v1);
    cudaGetSymbolAddress((void**)&p_mag, g_mag);
    cudaGetSymbolAddress((void**)&p_qd, g_qd);
    cudaGetSymbolAddress((void**)&p_s1g, g_s1g);
    cudaGetSymbolAddress((void**)&p_posret, g_posret);
    cudaGetSymbolAddress((void**)&p_ccat, g_ccat);
    cudaGetSymbolAddress((void**)&p_ln, g_ln);
    cudaGetSymbolAddress((void**)&p_h1, g_h1);
    cudaGetSymbolAddress((void**)&p_wt, g_wt);
    cudaGetSymbolAddress((void**)&p_cqp, g_cqp);
    cudaGetSymbolAddress((void**)&p_sqp, g_sqp);
    cudaGetSymbolAddress((void**)&p_csp, g_csp);
    cudaGetSymbolAddress((void**)&p_ssp, g_ssp);
    cudaGetSymbolAddress((void**)&p_bcat, g_bcat);

    float* wt_proj = p_wt + WT_PROJ;
    float* wt_o    = p_wt + WT_O;
    float* wt_s1   = p_wt + WT_S1;
    float* wt_s2   = p_wt + WT_S2;
    float* wt_t1   = p_wt + WT_T1;
    float* wt_t2   = p_wt + WT_T2;

    const int SMEM = 2 * STAGE_F * 4;  // 73728 B
    cudaFuncSetAttribute(mma_gemm, cudaFuncAttributeMaxDynamicSharedMemorySize, SMEM);

    // ---- batched transpose (tf32-rounded) ----
    TTable tt;
    tt.src[0] = w_v;  tt.dst[0] = wt_proj;              tt.K[0] = 512;  tt.N[0] = 512;
    tt.src[1] = w_m;  tt.dst[1] = wt_proj + 512 * 512;  tt.K[1] = 512;  tt.N[1] = 512;
    tt.src[2] = w_q;  tt.dst[2] = wt_proj + 1024 * 512; tt.K[2] = 512;  tt.N[2] = 512;
    tt.src[3] = w_ke; tt.dst[3] = wt_proj + 1536 * 512; tt.K[3] = 512;  tt.N[3] = 128;
    tt.src[4] = w_o;  tt.dst[4] = wt_o;                 tt.K[4] = 512;  tt.N[4] = 512;
    tt.src[5] = w_s1; tt.dst[5] = wt_s1;                tt.K[5] = 1024; tt.N[5] = 512;
    tt.src[6] = w_s2; tt.dst[6] = wt_s2;                tt.K[6] = 512;  tt.N[6] = 128;
    tt.src[7] = w_t1; tt.dst[7] = wt_t1;                tt.K[7] = 1024; tt.N[7] = 1024;
    tt.src[8] = w_t2; tt.dst[8] = wt_t2;                tt.K[8] = 1024; tt.N[8] = 512;
    int acc = 0;
    for (int i = 0; i < 9; i++) {
        tt.t0[i] = acc;
        acc += (tt.K[i] >> 5) * (tt.N[i] >> 5);
    }
    transpose_all<<<acc, 256>>>(tt);
    bias_concat<<<7, 256>>>(b_v, b_m, b_q, b_ke);

    dim3 tb(256);
    dim3 gScan(Bv * NCv, Dv / 128);

    phi_kernel<<<(Lv * Dv + 255) / 256, 256>>>(pos);
    ctx_p1<<<gScan, 128>>>(x);
    ctx_p2<<<(Bv * Dv + 255) / 256, 256>>>();
    ctx_p3<<<gScan, 128>>>(x);

    // merged projections: v | mag | qd | ke-sincos
    mma_gemm<<<dim3(13, 128), tb, SMEM>>>(x, wt_proj, p_bcat,
        p_v1, p_mag, p_qd, p_cqp, p_sqp, 512, 512, 6, ms);
    vg_kernel<<<Mv / 8, 256>>>(x, w_ve, b_ve, w_g, b_g);
    mma_gemm<<<dim3(4, 128), tb, SMEM>>>(p_xcat, wt_s1, b_s1,
        p_s1g, nullptr, nullptr, nullptr, nullptr, 1024, 512, 2, nullptr);
    mma_gemm<<<dim3(1, 128), tb, SMEM>>>(p_s1g, wt_s2, b_s2,
        p_csp, p_ssp, nullptr, nullptr, nullptr, 512, 128, 5, nullptr);

    // mem1 scan + pos_out
    mem1_p1<<<gScan, 128>>>();
    mem1_p2<<<(Bv * Dv + 255) / 256, 256>>>();
    mem1_p3<<<gScan, 128>>>(pos);
    mma_gemm<<<dim3(4, 128), tb, SMEM>>>(p_posret, wt_o, b_o,
        p_ccat, nullptr, nullptr, nullptr, nullptr, 512, 1024, 0, nullptr);

    // kv scan + retrieval + kv_out
    kv_p1<<<Bv * NCv, 256>>>();
    kv_p2<<<(Bv * Pv * Vv + 255) / 256, 256>>>();
    kv_p3<<<Bv * NCv, 256>>>();
    kvout_kernel<<<Mv / 32, 256>>>(w_kv, b_kv);

    // LN + output MLP + residual
    ln_kernel<<<Mv, 256>>>(lng, lnb);
    mma_gemm<<<dim3(8, 128), tb, SMEM>>>(p_ln, wt_t1, b_t1,
        p_h1, nullptr, nullptr, nullptr, nullptr, 1024, 1024, 2, nullptr);
    mma_gemm<<<dim3(4, 128), tb, SMEM>>>(p_h1, wt_t2, b_t2,
        out, nullptr, nullptr, nullptr, nullptr, 1024, 512, 4, x);
}